// round 13
// baseline (speedup 1.0000x reference)
#include <cuda_runtime.h>

#define NB 512
#define NA 32
#define ND 256
#define NN (NB*NA)            // 16384 nodes
#define NE 1048576            // edges
#define XO_ELEMS (NN*ND)      // 4194304
#define MASK_ELEMS (NB*NA*NA) // 524288
#define SLOT 192              // max in-degree slots per node (deg ~ Poisson(64))

typedef unsigned long long u64;

// ---------------- scratch (static device globals; no allocation) -------------
__device__ float g_Y[NN*ND];         // X @ W
__device__ float g_Xo_scratch[NN*ND];
__device__ float g_mask_scratch[MASK_ELEMS];
__device__ float g_dinv[NN];
__device__ int   g_deg[NN];          // memset to 0, then atomic slot counter == degree
__device__ int   g_slot[NN*SLOT];    // source node per slot (rows 768B-aligned)

// ---------------- helpers ----------------------------------------------------
__device__ __forceinline__ void fma4(float4& acc, float4 v, float c) {
    acc.x = fmaf(v.x, c, acc.x);
    acc.y = fmaf(v.y, c, acc.y);
    acc.z = fmaf(v.z, c, acc.z);
    acc.w = fmaf(v.w, c, acc.w);
}

__device__ __forceinline__ u64 pack_dup(float a) {
    u64 r;
    asm("mov.b64 %0, {%1, %1};" : "=l"(r) : "f"(a));
    return r;
}
__device__ __forceinline__ void ffma2(u64& d, u64 a, u64 b) {
    asm("fma.rn.f32x2 %0, %1, %2, %3;" : "=l"(d) : "l"(a), "l"(b), "l"(d));
}
__device__ __forceinline__ void unpack2(u64 v, float& lo, float& hi) {
    asm("mov.b64 {%0, %1}, %2;" : "=f"(lo), "=f"(hi) : "l"(v));
}

// ---------------- K1: single-pass slot scatter (histogram + scatter fused) ---
__global__ void k_scatter(const int* __restrict__ ei) {
    int e = blockIdx.x * blockDim.x + threadIdx.x;
    if (e < NE) {
        int s = ei[e];
        int t = ei[NE + e];
        int slot = atomicAdd(&g_deg[t], 1);
        if (slot < SLOT) g_slot[(size_t)t * SLOT + slot] = s;
    }
}

// ---------------- K1b: dinv from final degrees --------------------------------
__global__ void k_dinv() {
    int i = blockIdx.x * blockDim.x + threadIdx.x;
    if (i < NN) g_dinv[i] = rsqrtf((float)(g_deg[i] + 1));
}

// ---------------- K2: SGEMM Y[N,256]=X[N,256]*W[256,256] ----------------------
// 256x128 tile, 512 threads, 8x8 per thread, K-step 8, double-buffered smem.
// A tile stored in smem as PRE-DUPLICATED u64 pairs {a,a}: the FFMA2 inner
// loop reads operands directly (no per-kk mov.b64 packing). B fragments are
// read as packed pairs (bit-identical). 38 issue slots per kk per thread.
#define AS2_STRIDE 260   // u64 elements per k-row (256 rows + pad)
__global__ void __launch_bounds__(512) k_gemm(const float* __restrict__ X,
                                              const float* __restrict__ W) {
    __shared__ u64   As2[2][8][AS2_STRIDE];  // [k][m] duplicated pairs, padded
    __shared__ float Bs[2][8][128];          // [k][n]

    int tid = threadIdx.x;
    int m0 = blockIdx.x * 256;
    int n0 = blockIdx.y * 128;

    int arow = tid >> 1;          // 0..255
    int akk  = (tid & 1) * 4;     // 0 or 4
    int bkk  = tid >> 5;          // only tid<256 loads B: bkk 0..7
    int bnn  = (tid & 31) * 4;    // 0..124
    bool bload = (tid < 256);

    const float* Aptr = X + (size_t)(m0 + arow) * 256 + akk;
    const float* Bptr = W + (size_t)bkk * 256 + n0 + bnn;

    float4 av = *(const float4*)Aptr;
    float4 bv = bload ? *(const float4*)Bptr : make_float4(0.f, 0.f, 0.f, 0.f);
    int buf = 0;
    As2[buf][akk + 0][arow] = pack_dup(av.x);
    As2[buf][akk + 1][arow] = pack_dup(av.y);
    As2[buf][akk + 2][arow] = pack_dup(av.z);
    As2[buf][akk + 3][arow] = pack_dup(av.w);
    if (bload) *(float4*)&Bs[buf][bkk][bnn] = bv;
    __syncthreads();

    // packed accumulators: acc2[i][j] = {col 2j, col 2j+1} of row i
    u64 acc2[8][4];
#pragma unroll
    for (int i = 0; i < 8; ++i)
#pragma unroll
        for (int j = 0; j < 4; ++j) acc2[i][j] = 0ull;

    int tx = tid & 15;   // col group: cols tx*4 and 64+tx*4
    int ty = tid >> 4;   // row group: rows ty*4 and 128+ty*4

    for (int k0 = 8; k0 <= 256; k0 += 8) {
        if (k0 < 256) {
            av = *(const float4*)(Aptr + k0);
            if (bload) bv = *(const float4*)(Bptr + (size_t)k0 * 256);
        }
#pragma unroll
        for (int kk = 0; kk < 8; ++kk) {
            // A operands: duplicated pairs, broadcast LDS.128 (2 u64 each)
            ulonglong2 ap0 = *(const ulonglong2*)&As2[buf][kk][ty * 4 + 0];
            ulonglong2 ap1 = *(const ulonglong2*)&As2[buf][kk][ty * 4 + 2];
            ulonglong2 ap2 = *(const ulonglong2*)&As2[buf][kk][128 + ty * 4 + 0];
            ulonglong2 ap3 = *(const ulonglong2*)&As2[buf][kk][128 + ty * 4 + 2];
            u64 aa[8] = {ap0.x, ap0.y, ap1.x, ap1.y, ap2.x, ap2.y, ap3.x, ap3.y};
            // B fragments as packed pairs (same bit layout)
            ulonglong2 bp0 = *(const ulonglong2*)&Bs[buf][kk][tx * 4];
            ulonglong2 bp1 = *(const ulonglong2*)&Bs[buf][kk][64 + tx * 4];
            u64 bb[4] = {bp0.x, bp0.y, bp1.x, bp1.y};
#pragma unroll
            for (int i = 0; i < 8; ++i)
#pragma unroll
                for (int j = 0; j < 4; ++j)
                    ffma2(acc2[i][j], aa[i], bb[j]);
        }
        if (k0 < 256) {
            buf ^= 1;
            As2[buf][akk + 0][arow] = pack_dup(av.x);
            As2[buf][akk + 1][arow] = pack_dup(av.y);
            As2[buf][akk + 2][arow] = pack_dup(av.z);
            As2[buf][akk + 3][arow] = pack_dup(av.w);
            if (bload) *(float4*)&Bs[buf][bkk][bnn] = bv;
            __syncthreads();
        }
    }

#pragma unroll
    for (int i = 0; i < 8; ++i) {
        int m = m0 + ((i < 4) ? (ty * 4 + i) : (128 + ty * 4 + (i - 4)));
        float4 v0, v1;
        unpack2(acc2[i][0], v0.x, v0.y);
        unpack2(acc2[i][1], v0.z, v0.w);
        unpack2(acc2[i][2], v1.x, v1.y);
        unpack2(acc2[i][3], v1.z, v1.w);
        *(float4*)&g_Y[(size_t)m * 256 + n0 + tx * 4]      = v0;
        *(float4*)&g_Y[(size_t)m * 256 + n0 + 64 + tx * 4] = v1;
    }
}

// ---------------- K3: gather aggregation (warp per target node) --------------
// 8-edge unrolled: two int4 slot loads per iteration, then two batches of
// 8 independent LDG.128 to widen the per-warp load window (L2-latency bound).
__global__ void __launch_bounds__(256) k_aggregate(const float* __restrict__ bias,
                                                   float* __restrict__ Xo) {
    int warp = (blockIdx.x * blockDim.x + threadIdx.x) >> 5;
    int lane = threadIdx.x & 31;
    if (warp >= NN) return;

    float din = g_dinv[warp];
    const float4* yself = (const float4*)&g_Y[(size_t)warp * 256];
    float cself = din * din;
    float4 acc0 = make_float4(0.f, 0.f, 0.f, 0.f);
    float4 acc1 = make_float4(0.f, 0.f, 0.f, 0.f);
    fma4(acc0, yself[lane], cself);
    fma4(acc1, yself[lane + 32], cself);

    int deg = g_deg[warp];
    if (deg > SLOT) deg = SLOT;
    const int*  slots  = &g_slot[(size_t)warp * SLOT];
    const int4* slots4 = (const int4*)slots;   // row base is 768B-aligned

    int n8 = deg >> 3;
    for (int q = 0; q < n8; ++q) {
        int4 sa = slots4[2 * q];
        int4 sb = slots4[2 * q + 1];

        float c0 = g_dinv[sa.x] * din;
        float c1 = g_dinv[sa.y] * din;
        float c2 = g_dinv[sa.z] * din;
        float c3 = g_dinv[sa.w] * din;
        float c4 = g_dinv[sb.x] * din;
        float c5 = g_dinv[sb.y] * din;
        float c6 = g_dinv[sb.z] * din;
        float c7 = g_dinv[sb.w] * din;

        const float4* y0 = (const float4*)&g_Y[(size_t)sa.x * 256];
        const float4* y1 = (const float4*)&g_Y[(size_t)sa.y * 256];
        const float4* y2 = (const float4*)&g_Y[(size_t)sa.z * 256];
        const float4* y3 = (const float4*)&g_Y[(size_t)sa.w * 256];
        const float4* y4 = (const float4*)&g_Y[(size_t)sb.x * 256];
        const float4* y5 = (const float4*)&g_Y[(size_t)sb.y * 256];
        const float4* y6 = (const float4*)&g_Y[(size_t)sb.z * 256];
        const float4* y7 = (const float4*)&g_Y[(size_t)sb.w * 256];

        // batch 1: 8 independent first-half loads
        float4 a0 = y0[lane], a1 = y1[lane], a2 = y2[lane], a3 = y3[lane];
        float4 a4 = y4[lane], a5 = y5[lane], a6 = y6[lane], a7 = y7[lane];
        fma4(acc0, a0, c0); fma4(acc0, a1, c1);
        fma4(acc0, a2, c2); fma4(acc0, a3, c3);
        fma4(acc0, a4, c4); fma4(acc0, a5, c5);
        fma4(acc0, a6, c6); fma4(acc0, a7, c7);

        // batch 2: 8 independent second-half loads
        float4 b0 = y0[lane + 32], b1 = y1[lane + 32], b2 = y2[lane + 32], b3 = y3[lane + 32];
        float4 b4 = y4[lane + 32], b5 = y5[lane + 32], b6 = y6[lane + 32], b7 = y7[lane + 32];
        fma4(acc1, b0, c0); fma4(acc1, b1, c1);
        fma4(acc1, b2, c2); fma4(acc1, b3, c3);
        fma4(acc1, b4, c4); fma4(acc1, b5, c5);
        fma4(acc1, b6, c6); fma4(acc1, b7, c7);
    }
    for (int j = n8 << 3; j < deg; ++j) {
        int s0 = slots[j];
        float c0 = g_dinv[s0] * din;
        const float4* y0 = (const float4*)&g_Y[(size_t)s0 * 256];
        fma4(acc0, y0[lane], c0);
        fma4(acc1, y0[lane + 32], c0);
    }

    float4 bv0 = *(const float4*)&bias[lane * 4];
    float4 bv1 = *(const float4*)&bias[128 + lane * 4];
    acc0.x += bv0.x; acc0.y += bv0.y; acc0.z += bv0.z; acc0.w += bv0.w;
    acc1.x += bv1.x; acc1.y += bv1.y; acc1.z += bv1.z; acc1.w += bv1.w;

    float4* orow = (float4*)&Xo[(size_t)warp * 256];
    orow[lane] = acc0;
    orow[lane + 32] = acc1;
}

// ---------------- K4: per-batch adjacency mask -------------------------------
// 1 block per batch, 512 threads = 16 warps; warp w -> rows 2w, 2w+1; lane=col.
#define XS_STRIDE 260  // 16B-aligned rows; conflict-free LDS.128 phases
__global__ void __launch_bounds__(512) k_adj(const float* __restrict__ Xo,
                                             float* __restrict__ mask) {
    __shared__ float xs[32 * XS_STRIDE];
    __shared__ float sqv[32];
    int b = blockIdx.x;
    int tid = threadIdx.x;
    int warp = tid >> 5;
    int lane = tid & 31;

    const float* xb = &Xo[(size_t)b * NA * ND];
    for (int e = tid; e < NA * ND; e += 512) {
        int r = e >> 8;
        int c = e & 255;
        xs[r * XS_STRIDE + c] = xb[e];
    }
    __syncthreads();

    // squared norms: warp w handles rows 2w, 2w+1
#pragma unroll
    for (int i = 0; i < 2; ++i) {
        int r = warp * 2 + i;
        float s = 0.f;
        for (int k = lane; k < 256; k += 32) {
            float v = xs[r * XS_STRIDE + k];
            s = fmaf(v, v, s);
        }
#pragma unroll
        for (int off = 16; off > 0; off >>= 1)
            s += __shfl_xor_sync(0xFFFFFFFFu, s, off);
        if (lane == 0) sqv[r] = s;
    }
    __syncthreads();

    int a0 = warp * 2;
    int c = lane;
    const float* x0 = &xs[(a0 + 0) * XS_STRIDE];
    const float* x1 = &xs[(a0 + 1) * XS_STRIDE];
    const float* xc = &xs[c * XS_STRIDE];

    float d0 = 0.f, d1 = 0.f;
#pragma unroll
    for (int k = 0; k < 256; k += 4) {
        float4 vc = *(const float4*)&xc[k];
        float4 v0 = *(const float4*)&x0[k];
        float4 v1 = *(const float4*)&x1[k];
        d0 = fmaf(v0.x, vc.x, d0); d0 = fmaf(v0.y, vc.y, d0);
        d0 = fmaf(v0.z, vc.z, d0); d0 = fmaf(v0.w, vc.w, d0);
        d1 = fmaf(v1.x, vc.x, d1); d1 = fmaf(v1.y, vc.y, d1);
        d1 = fmaf(v1.z, vc.z, d1); d1 = fmaf(v1.w, vc.w, d1);
    }

    float sc = sqv[c];
    float s0 = sqv[a0 + 0] + sc - 2.0f * d0;
    float s1 = sqv[a0 + 1] + sc - 2.0f * d1;

    float mn0 = s0, mx0 = s0, mn1 = s1, mx1 = s1;
#pragma unroll
    for (int off = 16; off > 0; off >>= 1) {
        mn0 = fminf(mn0, __shfl_xor_sync(0xFFFFFFFFu, mn0, off));
        mx0 = fmaxf(mx0, __shfl_xor_sync(0xFFFFFFFFu, mx0, off));
        mn1 = fminf(mn1, __shfl_xor_sync(0xFFFFFFFFu, mn1, off));
        mx1 = fmaxf(mx1, __shfl_xor_sync(0xFFFFFFFFu, mx1, off));
    }

    float* mrow = &mask[(size_t)b * (NA * NA)];
    mrow[(a0 + 0) * NA + c] = ((s0 - mn0) / (mx0 - mn0 + 1e-5f) > 0.5f) ? 1.0f : 0.0f;
    mrow[(a0 + 1) * NA + c] = ((s1 - mn1) / (mx1 - mn1 + 1e-5f) > 0.5f) ? 1.0f : 0.0f;
}

// ---------------- launch ------------------------------------------------------
extern "C" void kernel_launch(void* const* d_in, const int* in_sizes, int n_in,
                              void* d_out, int out_size) {
    const float* X  = (const float*)d_in[0];
    const int*   ei = (const int*)d_in[1];
    const float* W  = (const float*)d_in[2];
    const float* bv = (const float*)d_in[3];
    float* out = (float*)d_out;

    float* Xo;
    float* mask;
    if (out_size >= XO_ELEMS + MASK_ELEMS) {
        Xo = out;
        mask = out + XO_ELEMS;
    } else if (out_size >= XO_ELEMS) {
        Xo = out;
        float* dummy; cudaGetSymbolAddress((void**)&dummy, g_mask_scratch);
        mask = dummy;
    } else {
        float* dummy; cudaGetSymbolAddress((void**)&dummy, g_Xo_scratch);
        Xo = dummy;
        mask = out;
    }

    // one-time host-side infra (no device allocation)
    static cudaStream_t s2 = nullptr;
    static cudaEvent_t evFork = nullptr, evJoin = nullptr;
    if (s2 == nullptr) {
        cudaStreamCreateWithFlags(&s2, cudaStreamNonBlocking);
        cudaEventCreateWithFlags(&evFork, cudaEventDisableTiming);
        cudaEventCreateWithFlags(&evJoin, cudaEventDisableTiming);
    }

    void* degp;
    cudaGetSymbolAddress(&degp, g_deg);

    // fork: GEMM on s2 runs concurrently with memset+scatter+dinv on default
    cudaEventRecord(evFork, 0);
    cudaStreamWaitEvent(s2, evFork, 0);
    dim3 gg(NN / 256, 256 / 128);       // (64, 2) = 128 CTAs, single wave
    k_gemm<<<gg, 512, 0, s2>>>(X, W);
    cudaEventRecord(evJoin, s2);

    cudaMemsetAsync(degp, 0, NN * sizeof(int));
    k_scatter<<<NE / 256, 256>>>(ei);
    k_dinv<<<NN / 512, 512>>>();

    // join: aggregate needs both Y (s2) and slots/dinv (default)
    cudaStreamWaitEvent(0, evJoin, 0);
    k_aggregate<<<(NN * 32) / 256, 256>>>(bv, Xo);
    k_adj<<<NB, 512>>>(Xo, mask);
}

// round 14
// speedup vs baseline: 1.0718x; 1.0718x over previous
#include <cuda_runtime.h>

#define NB 512
#define NA 32
#define ND 256
#define NN (NB*NA)            // 16384 nodes
#define NE 1048576            // edges
#define XO_ELEMS (NN*ND)      // 4194304
#define MASK_ELEMS (NB*NA*NA) // 524288
#define SLOT 192              // max in-degree slots per node (deg ~ Poisson(64))

typedef unsigned long long u64;

// ---------------- scratch (static device globals; no allocation) -------------
__device__ float g_Y[NN*ND];         // X @ W
__device__ float g_Xo_scratch[NN*ND];
__device__ float g_mask_scratch[MASK_ELEMS];
__device__ float g_dinv[NN];
__device__ int   g_deg[NN];          // memset to 0, then atomic slot counter == degree
__device__ int   g_slot[NN*SLOT];    // source node per slot (rows 768B-aligned)

// ---------------- helpers ----------------------------------------------------
__device__ __forceinline__ void fma4(float4& acc, float4 v, float c) {
    acc.x = fmaf(v.x, c, acc.x);
    acc.y = fmaf(v.y, c, acc.y);
    acc.z = fmaf(v.z, c, acc.z);
    acc.w = fmaf(v.w, c, acc.w);
}

__device__ __forceinline__ u64 pack_dup(float a) {
    u64 r;
    asm("mov.b64 %0, {%1, %1};" : "=l"(r) : "f"(a));
    return r;
}
__device__ __forceinline__ void ffma2(u64& d, u64 a, u64 b) {
    asm("fma.rn.f32x2 %0, %1, %2, %3;" : "=l"(d) : "l"(a), "l"(b), "l"(d));
}
__device__ __forceinline__ void unpack2(u64 v, float& lo, float& hi) {
    asm("mov.b64 {%0, %1}, %2;" : "=f"(lo), "=f"(hi) : "l"(v));
}

// ---------------- K1: single-pass slot scatter (histogram + scatter fused) ---
__global__ void k_scatter(const int* __restrict__ ei) {
    int e = blockIdx.x * blockDim.x + threadIdx.x;
    if (e < NE) {
        int s = ei[e];
        int t = ei[NE + e];
        int slot = atomicAdd(&g_deg[t], 1);
        if (slot < SLOT) g_slot[(size_t)t * SLOT + slot] = s;
    }
}

// ---------------- K1b: dinv from final degrees --------------------------------
__global__ void k_dinv() {
    int i = blockIdx.x * blockDim.x + threadIdx.x;
    if (i < NN) g_dinv[i] = rsqrtf((float)(g_deg[i] + 1));
}

// ---------------- K2: SGEMM Y[N,256]=X[N,256]*W[256,256] ----------------------
// 256x128 tile, 512 threads, 8x8 per thread, K-step 8, double-buffered smem.
// Inner loop uses packed fma.rn.f32x2 (FFMA2). Grid = (64, 2), one wave.
// (Exact R12 winner version.)
#define AS_STRIDE 260
__global__ void __launch_bounds__(512) k_gemm(const float* __restrict__ X,
                                              const float* __restrict__ W) {
    __shared__ float As[2][8][AS_STRIDE];  // [k][m] transposed, padded
    __shared__ float Bs[2][8][128];        // [k][n]

    int tid = threadIdx.x;
    int m0 = blockIdx.x * 256;
    int n0 = blockIdx.y * 128;

    int arow = tid >> 1;          // 0..255
    int akk  = (tid & 1) * 4;     // 0 or 4
    int bkk  = tid >> 5;          // only tid<256 loads B: bkk 0..7
    int bnn  = (tid & 31) * 4;    // 0..124
    bool bload = (tid < 256);

    const float* Aptr = X + (size_t)(m0 + arow) * 256 + akk;
    const float* Bptr = W + (size_t)bkk * 256 + n0 + bnn;

    float4 av = *(const float4*)Aptr;
    float4 bv = bload ? *(const float4*)Bptr : make_float4(0.f, 0.f, 0.f, 0.f);
    int buf = 0;
    As[buf][akk + 0][arow] = av.x;
    As[buf][akk + 1][arow] = av.y;
    As[buf][akk + 2][arow] = av.z;
    As[buf][akk + 3][arow] = av.w;
    if (bload) *(float4*)&Bs[buf][bkk][bnn] = bv;
    __syncthreads();

    // packed accumulators: acc2[i][j] = {col 2j, col 2j+1} of row i
    u64 acc2[8][4];
#pragma unroll
    for (int i = 0; i < 8; ++i)
#pragma unroll
        for (int j = 0; j < 4; ++j) acc2[i][j] = 0ull;

    int tx = tid & 15;   // col group: cols tx*4 and 64+tx*4
    int ty = tid >> 4;   // row group: rows ty*4 and 128+ty*4

    for (int k0 = 8; k0 <= 256; k0 += 8) {
        if (k0 < 256) {
            av = *(const float4*)(Aptr + k0);
            if (bload) bv = *(const float4*)(Bptr + (size_t)k0 * 256);
        }
#pragma unroll
        for (int kk = 0; kk < 8; ++kk) {
            float4 a0 = *(const float4*)&As[buf][kk][ty * 4];
            float4 a1 = *(const float4*)&As[buf][kk][128 + ty * 4];
            ulonglong2 bp0 = *(const ulonglong2*)&Bs[buf][kk][tx * 4];
            ulonglong2 bp1 = *(const ulonglong2*)&Bs[buf][kk][64 + tx * 4];
            u64 bb[4] = {bp0.x, bp0.y, bp1.x, bp1.y};
            u64 aa[8];
            aa[0] = pack_dup(a0.x); aa[1] = pack_dup(a0.y);
            aa[2] = pack_dup(a0.z); aa[3] = pack_dup(a0.w);
            aa[4] = pack_dup(a1.x); aa[5] = pack_dup(a1.y);
            aa[6] = pack_dup(a1.z); aa[7] = pack_dup(a1.w);
#pragma unroll
            for (int i = 0; i < 8; ++i)
#pragma unroll
                for (int j = 0; j < 4; ++j)
                    ffma2(acc2[i][j], aa[i], bb[j]);
        }
        if (k0 < 256) {
            buf ^= 1;
            As[buf][akk + 0][arow] = av.x;
            As[buf][akk + 1][arow] = av.y;
            As[buf][akk + 2][arow] = av.z;
            As[buf][akk + 3][arow] = av.w;
            if (bload) *(float4*)&Bs[buf][bkk][bnn] = bv;
            __syncthreads();
        }
    }

#pragma unroll
    for (int i = 0; i < 8; ++i) {
        int m = m0 + ((i < 4) ? (ty * 4 + i) : (128 + ty * 4 + (i - 4)));
        float4 v0, v1;
        unpack2(acc2[i][0], v0.x, v0.y);
        unpack2(acc2[i][1], v0.z, v0.w);
        unpack2(acc2[i][2], v1.x, v1.y);
        unpack2(acc2[i][3], v1.z, v1.w);
        *(float4*)&g_Y[(size_t)m * 256 + n0 + tx * 4]      = v0;
        *(float4*)&g_Y[(size_t)m * 256 + n0 + 64 + tx * 4] = v1;
    }
}

// ---------------- K3: gather aggregation (2 warps per target node) -----------
// Warp pair splits the 256-dim row: each warp owns 128 dims (1 float4/lane).
// 4-edge unrolled int4 slot loads with prefetch. Halved per-thread registers
// vs 1-warp/node -> occupancy cap (8 CTAs/SM), more loads in flight per SM.
__global__ void __launch_bounds__(256) k_aggregate(const float* __restrict__ bias,
                                                   float* __restrict__ Xo) {
    int gwarp = (blockIdx.x * blockDim.x + threadIdx.x) >> 5;
    int lane  = threadIdx.x & 31;
    int node  = gwarp >> 1;
    int ofs   = ((gwarp & 1) << 5) + lane;   // float4 index 0..63 within row
    if (node >= NN) return;

    float din = g_dinv[node];
    float cself = din * din;
    float4 acc = make_float4(0.f, 0.f, 0.f, 0.f);
    fma4(acc, ((const float4*)&g_Y[(size_t)node * 256])[ofs], cself);

    int deg = g_deg[node];
    if (deg > SLOT) deg = SLOT;
    const int*  slots  = &g_slot[(size_t)node * SLOT];
    const int4* slots4 = (const int4*)slots;   // row base is 768B-aligned

    int nq = deg >> 2;
    if (nq > 0) {
        int4 s4 = slots4[0];
        for (int q = 0; q < nq; ++q) {
            int4 cur = s4;
            if (q + 1 < nq) s4 = slots4[q + 1];   // prefetch next indices

            float c0 = g_dinv[cur.x] * din;
            float c1 = g_dinv[cur.y] * din;
            float c2 = g_dinv[cur.z] * din;
            float c3 = g_dinv[cur.w] * din;

            // 4 independent 16B loads
            float4 a0 = ((const float4*)&g_Y[(size_t)cur.x * 256])[ofs];
            float4 a1 = ((const float4*)&g_Y[(size_t)cur.y * 256])[ofs];
            float4 a2 = ((const float4*)&g_Y[(size_t)cur.z * 256])[ofs];
            float4 a3 = ((const float4*)&g_Y[(size_t)cur.w * 256])[ofs];

            fma4(acc, a0, c0);
            fma4(acc, a1, c1);
            fma4(acc, a2, c2);
            fma4(acc, a3, c3);
        }
    }
    for (int j = nq << 2; j < deg; ++j) {
        int s0 = slots[j];
        float c0 = g_dinv[s0] * din;
        fma4(acc, ((const float4*)&g_Y[(size_t)s0 * 256])[ofs], c0);
    }

    float4 bv = ((const float4*)bias)[ofs];
    acc.x += bv.x; acc.y += bv.y; acc.z += bv.z; acc.w += bv.w;

    ((float4*)&Xo[(size_t)node * 256])[ofs] = acc;
}

// ---------------- K4: per-batch adjacency mask -------------------------------
// 1 block per batch, 512 threads = 16 warps; warp w -> rows 2w, 2w+1; lane=col.
#define XS_STRIDE 260  // 16B-aligned rows; conflict-free LDS.128 phases
__global__ void __launch_bounds__(512) k_adj(const float* __restrict__ Xo,
                                             float* __restrict__ mask) {
    __shared__ float xs[32 * XS_STRIDE];
    __shared__ float sqv[32];
    int b = blockIdx.x;
    int tid = threadIdx.x;
    int warp = tid >> 5;
    int lane = tid & 31;

    const float* xb = &Xo[(size_t)b * NA * ND];
    for (int e = tid; e < NA * ND; e += 512) {
        int r = e >> 8;
        int c = e & 255;
        xs[r * XS_STRIDE + c] = xb[e];
    }
    __syncthreads();

    // squared norms: warp w handles rows 2w, 2w+1
#pragma unroll
    for (int i = 0; i < 2; ++i) {
        int r = warp * 2 + i;
        float s = 0.f;
        for (int k = lane; k < 256; k += 32) {
            float v = xs[r * XS_STRIDE + k];
            s = fmaf(v, v, s);
        }
#pragma unroll
        for (int off = 16; off > 0; off >>= 1)
            s += __shfl_xor_sync(0xFFFFFFFFu, s, off);
        if (lane == 0) sqv[r] = s;
    }
    __syncthreads();

    int a0 = warp * 2;
    int c = lane;
    const float* x0 = &xs[(a0 + 0) * XS_STRIDE];
    const float* x1 = &xs[(a0 + 1) * XS_STRIDE];
    const float* xc = &xs[c * XS_STRIDE];

    float d0 = 0.f, d1 = 0.f;
#pragma unroll
    for (int k = 0; k < 256; k += 4) {
        float4 vc = *(const float4*)&xc[k];
        float4 v0 = *(const float4*)&x0[k];
        float4 v1 = *(const float4*)&x1[k];
        d0 = fmaf(v0.x, vc.x, d0); d0 = fmaf(v0.y, vc.y, d0);
        d0 = fmaf(v0.z, vc.z, d0); d0 = fmaf(v0.w, vc.w, d0);
        d1 = fmaf(v1.x, vc.x, d1); d1 = fmaf(v1.y, vc.y, d1);
        d1 = fmaf(v1.z, vc.z, d1); d1 = fmaf(v1.w, vc.w, d1);
    }

    float sc = sqv[c];
    float s0 = sqv[a0 + 0] + sc - 2.0f * d0;
    float s1 = sqv[a0 + 1] + sc - 2.0f * d1;

    float mn0 = s0, mx0 = s0, mn1 = s1, mx1 = s1;
#pragma unroll
    for (int off = 16; off > 0; off >>= 1) {
        mn0 = fminf(mn0, __shfl_xor_sync(0xFFFFFFFFu, mn0, off));
        mx0 = fmaxf(mx0, __shfl_xor_sync(0xFFFFFFFFu, mx0, off));
        mn1 = fminf(mn1, __shfl_xor_sync(0xFFFFFFFFu, mn1, off));
        mx1 = fmaxf(mx1, __shfl_xor_sync(0xFFFFFFFFu, mx1, off));
    }

    float* mrow = &mask[(size_t)b * (NA * NA)];
    mrow[(a0 + 0) * NA + c] = ((s0 - mn0) / (mx0 - mn0 + 1e-5f) > 0.5f) ? 1.0f : 0.0f;
    mrow[(a0 + 1) * NA + c] = ((s1 - mn1) / (mx1 - mn1 + 1e-5f) > 0.5f) ? 1.0f : 0.0f;
}

// ---------------- launch ------------------------------------------------------
extern "C" void kernel_launch(void* const* d_in, const int* in_sizes, int n_in,
                              void* d_out, int out_size) {
    const float* X  = (const float*)d_in[0];
    const int*   ei = (const int*)d_in[1];
    const float* W  = (const float*)d_in[2];
    const float* bv = (const float*)d_in[3];
    float* out = (float*)d_out;

    float* Xo;
    float* mask;
    if (out_size >= XO_ELEMS + MASK_ELEMS) {
        Xo = out;
        mask = out + XO_ELEMS;
    } else if (out_size >= XO_ELEMS) {
        Xo = out;
        float* dummy; cudaGetSymbolAddress((void**)&dummy, g_mask_scratch);
        mask = dummy;
    } else {
        float* dummy; cudaGetSymbolAddress((void**)&dummy, g_Xo_scratch);
        Xo = dummy;
        mask = out;
    }

    // one-time host-side infra (no device allocation)
    static cudaStream_t s2 = nullptr;
    static cudaEvent_t evFork = nullptr, evJoin = nullptr;
    if (s2 == nullptr) {
        cudaStreamCreateWithFlags(&s2, cudaStreamNonBlocking);
        cudaEventCreateWithFlags(&evFork, cudaEventDisableTiming);
        cudaEventCreateWithFlags(&evJoin, cudaEventDisableTiming);
    }

    void* degp;
    cudaGetSymbolAddress(&degp, g_deg);

    // fork: GEMM on s2 runs concurrently with memset+scatter+dinv on default
    cudaEventRecord(evFork, 0);
    cudaStreamWaitEvent(s2, evFork, 0);
    dim3 gg(NN / 256, 256 / 128);       // (64, 2) = 128 CTAs, single wave
    k_gemm<<<gg, 512, 0, s2>>>(X, W);
    cudaEventRecord(evJoin, s2);

    cudaMemsetAsync(degp, 0, NN * sizeof(int));
    k_scatter<<<NE / 256, 256>>>(ei);
    k_dinv<<<NN / 512, 512>>>();

    // join: aggregate needs both Y (s2) and slots/dinv (default)
    cudaStreamWaitEvent(0, evJoin, 0);
    k_aggregate<<<(NN * 2 * 32) / 256, 256>>>(bv, Xo);
    k_adj<<<NB, 512>>>(Xo, mask);
}

// round 15
// speedup vs baseline: 1.1647x; 1.0867x over previous
#include <cuda_runtime.h>

#define NB 512
#define NA 32
#define ND 256
#define NN (NB*NA)            // 16384 nodes
#define NE 1048576            // edges
#define XO_ELEMS (NN*ND)      // 4194304
#define MASK_ELEMS (NB*NA*NA) // 524288
#define SLOT 192              // max in-degree slots per node (deg ~ Poisson(64))

typedef unsigned long long u64;

// ---------------- scratch (static device globals; no allocation) -------------
__device__ float g_Y[NN*ND];         // X @ W
__device__ float g_Xo_scratch[NN*ND];
__device__ float g_mask_scratch[MASK_ELEMS];
__device__ float g_dinv[NN];
__device__ int   g_deg[NN];          // memset to 0, then atomic slot counter == degree
__device__ int   g_slot[NN*SLOT];    // source node per slot (rows 768B-aligned)

// ---------------- helpers ----------------------------------------------------
__device__ __forceinline__ void fma4(float4& acc, float4 v, float c) {
    acc.x = fmaf(v.x, c, acc.x);
    acc.y = fmaf(v.y, c, acc.y);
    acc.z = fmaf(v.z, c, acc.z);
    acc.w = fmaf(v.w, c, acc.w);
}

__device__ __forceinline__ u64 pack_dup(float a) {
    u64 r;
    asm("mov.b64 %0, {%1, %1};" : "=l"(r) : "f"(a));
    return r;
}
__device__ __forceinline__ void ffma2(u64& d, u64 a, u64 b) {
    asm("fma.rn.f32x2 %0, %1, %2, %3;" : "=l"(d) : "l"(a), "l"(b), "l"(d));
}
__device__ __forceinline__ void unpack2(u64 v, float& lo, float& hi) {
    asm("mov.b64 {%0, %1}, %2;" : "=f"(lo), "=f"(hi) : "l"(v));
}

// ---------------- K1: single-pass slot scatter (histogram + scatter fused) ---
__global__ void k_scatter(const int* __restrict__ ei) {
    int e = blockIdx.x * blockDim.x + threadIdx.x;
    if (e < NE) {
        int s = ei[e];
        int t = ei[NE + e];
        int slot = atomicAdd(&g_deg[t], 1);
        if (slot < SLOT) g_slot[(size_t)t * SLOT + slot] = s;
    }
}

// ---------------- K1b: dinv from final degrees --------------------------------
__global__ void k_dinv() {
    int i = blockIdx.x * blockDim.x + threadIdx.x;
    if (i < NN) g_dinv[i] = rsqrtf((float)(g_deg[i] + 1));
}

// ---------------- K2: SGEMM Y[N,256]=X[N,256]*W[256,256] ----------------------
// 128x128 tile, 256 threads, 8x8 per thread, K-step 8, double-buffered smem,
// FFMA2 inner loop. Grid = (128, 2) = 256 CTAs, 2 CTAs/SM (32 warps/SM) ->
// covers all 148 SMs and hides LDS/pipe latency (the 128-CTA version left
// 20 SMs idle and ran 1 CTA/SM).
#define AS_STRIDE 132
__global__ void __launch_bounds__(256, 2) k_gemm(const float* __restrict__ X,
                                                 const float* __restrict__ W) {
    __shared__ float As[2][8][AS_STRIDE];  // [k][m] transposed, padded
    __shared__ float Bs[2][8][128];        // [k][n]

    int tid = threadIdx.x;
    int m0 = blockIdx.x * 128;
    int n0 = blockIdx.y * 128;

    int arow = tid >> 1;          // 0..127
    int akk  = (tid & 1) * 4;     // 0 or 4
    int bkk  = tid >> 5;          // 0..7
    int bnn  = (tid & 31) * 4;    // 0..124

    const float* Aptr = X + (size_t)(m0 + arow) * 256 + akk;
    const float* Bptr = W + (size_t)bkk * 256 + n0 + bnn;

    float4 av = *(const float4*)Aptr;
    float4 bv = *(const float4*)Bptr;
    int buf = 0;
    As[buf][akk + 0][arow] = av.x;
    As[buf][akk + 1][arow] = av.y;
    As[buf][akk + 2][arow] = av.z;
    As[buf][akk + 3][arow] = av.w;
    *(float4*)&Bs[buf][bkk][bnn] = bv;
    __syncthreads();

    // packed accumulators: acc2[i][j] = {col 2j, col 2j+1} of row i
    u64 acc2[8][4];
#pragma unroll
    for (int i = 0; i < 8; ++i)
#pragma unroll
        for (int j = 0; j < 4; ++j) acc2[i][j] = 0ull;

    int tx = tid & 15;   // col group: cols tx*4 and 64+tx*4
    int ty = tid >> 4;   // row group: rows ty*4 and 64+ty*4

    for (int k0 = 8; k0 <= 256; k0 += 8) {
        if (k0 < 256) {
            av = *(const float4*)(Aptr + k0);
            bv = *(const float4*)(Bptr + (size_t)k0 * 256);
        }
#pragma unroll
        for (int kk = 0; kk < 8; ++kk) {
            float4 a0 = *(const float4*)&As[buf][kk][ty * 4];
            float4 a1 = *(const float4*)&As[buf][kk][64 + ty * 4];
            ulonglong2 bp0 = *(const ulonglong2*)&Bs[buf][kk][tx * 4];
            ulonglong2 bp1 = *(const ulonglong2*)&Bs[buf][kk][64 + tx * 4];
            u64 bb[4] = {bp0.x, bp0.y, bp1.x, bp1.y};
            u64 aa[8];
            aa[0] = pack_dup(a0.x); aa[1] = pack_dup(a0.y);
            aa[2] = pack_dup(a0.z); aa[3] = pack_dup(a0.w);
            aa[4] = pack_dup(a1.x); aa[5] = pack_dup(a1.y);
            aa[6] = pack_dup(a1.z); aa[7] = pack_dup(a1.w);
#pragma unroll
            for (int i = 0; i < 8; ++i)
#pragma unroll
                for (int j = 0; j < 4; ++j)
                    ffma2(acc2[i][j], aa[i], bb[j]);
        }
        if (k0 < 256) {
            buf ^= 1;
            As[buf][akk + 0][arow] = av.x;
            As[buf][akk + 1][arow] = av.y;
            As[buf][akk + 2][arow] = av.z;
            As[buf][akk + 3][arow] = av.w;
            *(float4*)&Bs[buf][bkk][bnn] = bv;
            __syncthreads();
        }
    }

#pragma unroll
    for (int i = 0; i < 8; ++i) {
        int m = m0 + ((i < 4) ? (ty * 4 + i) : (64 + ty * 4 + (i - 4)));
        float4 v0, v1;
        unpack2(acc2[i][0], v0.x, v0.y);
        unpack2(acc2[i][1], v0.z, v0.w);
        unpack2(acc2[i][2], v1.x, v1.y);
        unpack2(acc2[i][3], v1.z, v1.w);
        *(float4*)&g_Y[(size_t)m * 256 + n0 + tx * 4]      = v0;
        *(float4*)&g_Y[(size_t)m * 256 + n0 + 64 + tx * 4] = v1;
    }
}

// ---------------- K3: gather aggregation (warp per target node) --------------
// 4-edge unrolled: int4 slot loads (prefetched), 16 independent LDG.128 per
// iteration. (Exact R11/R12 winner form — measured floor ~63us.)
__global__ void __launch_bounds__(256) k_aggregate(const float* __restrict__ bias,
                                                   float* __restrict__ Xo) {
    int warp = (blockIdx.x * blockDim.x + threadIdx.x) >> 5;
    int lane = threadIdx.x & 31;
    if (warp >= NN) return;

    float din = g_dinv[warp];
    const float4* yself = (const float4*)&g_Y[(size_t)warp * 256];
    float cself = din * din;
    float4 acc0 = make_float4(0.f, 0.f, 0.f, 0.f);
    float4 acc1 = make_float4(0.f, 0.f, 0.f, 0.f);
    fma4(acc0, yself[lane], cself);
    fma4(acc1, yself[lane + 32], cself);

    int deg = g_deg[warp];
    if (deg > SLOT) deg = SLOT;
    const int*  slots  = &g_slot[(size_t)warp * SLOT];
    const int4* slots4 = (const int4*)slots;   // row base is 768B-aligned

    int nq = deg >> 2;
    if (nq > 0) {
        int4 s4 = slots4[0];
        for (int q = 0; q < nq; ++q) {
            int4 cur = s4;
            if (q + 1 < nq) s4 = slots4[q + 1];   // prefetch next indices

            float c0 = g_dinv[cur.x] * din;
            float c1 = g_dinv[cur.y] * din;
            float c2 = g_dinv[cur.z] * din;
            float c3 = g_dinv[cur.w] * din;

            const float4* y0 = (const float4*)&g_Y[(size_t)cur.x * 256];
            const float4* y1 = (const float4*)&g_Y[(size_t)cur.y * 256];
            const float4* y2 = (const float4*)&g_Y[(size_t)cur.z * 256];
            const float4* y3 = (const float4*)&g_Y[(size_t)cur.w * 256];

            float4 a0 = y0[lane],      a1 = y1[lane],      a2 = y2[lane],      a3 = y3[lane];
            float4 b0 = y0[lane + 32], b1 = y1[lane + 32], b2 = y2[lane + 32], b3 = y3[lane + 32];

            fma4(acc0, a0, c0); fma4(acc1, b0, c0);
            fma4(acc0, a1, c1); fma4(acc1, b1, c1);
            fma4(acc0, a2, c2); fma4(acc1, b2, c2);
            fma4(acc0, a3, c3); fma4(acc1, b3, c3);
        }
    }
    for (int j = nq << 2; j < deg; ++j) {
        int s0 = slots[j];
        float c0 = g_dinv[s0] * din;
        const float4* y0 = (const float4*)&g_Y[(size_t)s0 * 256];
        fma4(acc0, y0[lane], c0);
        fma4(acc1, y0[lane + 32], c0);
    }

    float4 bv0 = *(const float4*)&bias[lane * 4];
    float4 bv1 = *(const float4*)&bias[128 + lane * 4];
    acc0.x += bv0.x; acc0.y += bv0.y; acc0.z += bv0.z; acc0.w += bv0.w;
    acc1.x += bv1.x; acc1.y += bv1.y; acc1.z += bv1.z; acc1.w += bv1.w;

    float4* orow = (float4*)&Xo[(size_t)warp * 256];
    orow[lane] = acc0;
    orow[lane + 32] = acc1;
}

// ---------------- K4: per-batch adjacency mask -------------------------------
// 1 block per batch, 512 threads = 16 warps; warp w -> rows 2w, 2w+1; lane=col.
#define XS_STRIDE 260  // 16B-aligned rows; conflict-free LDS.128 phases
__global__ void __launch_bounds__(512) k_adj(const float* __restrict__ Xo,
                                             float* __restrict__ mask) {
    __shared__ float xs[32 * XS_STRIDE];
    __shared__ float sqv[32];
    int b = blockIdx.x;
    int tid = threadIdx.x;
    int warp = tid >> 5;
    int lane = tid & 31;

    const float* xb = &Xo[(size_t)b * NA * ND];
    for (int e = tid; e < NA * ND; e += 512) {
        int r = e >> 8;
        int c = e & 255;
        xs[r * XS_STRIDE + c] = xb[e];
    }
    __syncthreads();

    // squared norms: warp w handles rows 2w, 2w+1
#pragma unroll
    for (int i = 0; i < 2; ++i) {
        int r = warp * 2 + i;
        float s = 0.f;
        for (int k = lane; k < 256; k += 32) {
            float v = xs[r * XS_STRIDE + k];
            s = fmaf(v, v, s);
        }
#pragma unroll
        for (int off = 16; off > 0; off >>= 1)
            s += __shfl_xor_sync(0xFFFFFFFFu, s, off);
        if (lane == 0) sqv[r] = s;
    }
    __syncthreads();

    int a0 = warp * 2;
    int c = lane;
    const float* x0 = &xs[(a0 + 0) * XS_STRIDE];
    const float* x1 = &xs[(a0 + 1) * XS_STRIDE];
    const float* xc = &xs[c * XS_STRIDE];

    float d0 = 0.f, d1 = 0.f;
#pragma unroll
    for (int k = 0; k < 256; k += 4) {
        float4 vc = *(const float4*)&xc[k];
        float4 v0 = *(const float4*)&x0[k];
        float4 v1 = *(const float4*)&x1[k];
        d0 = fmaf(v0.x, vc.x, d0); d0 = fmaf(v0.y, vc.y, d0);
        d0 = fmaf(v0.z, vc.z, d0); d0 = fmaf(v0.w, vc.w, d0);
        d1 = fmaf(v1.x, vc.x, d1); d1 = fmaf(v1.y, vc.y, d1);
        d1 = fmaf(v1.z, vc.z, d1); d1 = fmaf(v1.w, vc.w, d1);
    }

    float sc = sqv[c];
    float s0 = sqv[a0 + 0] + sc - 2.0f * d0;
    float s1 = sqv[a0 + 1] + sc - 2.0f * d1;

    float mn0 = s0, mx0 = s0, mn1 = s1, mx1 = s1;
#pragma unroll
    for (int off = 16; off > 0; off >>= 1) {
        mn0 = fminf(mn0, __shfl_xor_sync(0xFFFFFFFFu, mn0, off));
        mx0 = fmaxf(mx0, __shfl_xor_sync(0xFFFFFFFFu, mx0, off));
        mn1 = fminf(mn1, __shfl_xor_sync(0xFFFFFFFFu, mn1, off));
        mx1 = fmaxf(mx1, __shfl_xor_sync(0xFFFFFFFFu, mx1, off));
    }

    float* mrow = &mask[(size_t)b * (NA * NA)];
    mrow[(a0 + 0) * NA + c] = ((s0 - mn0) / (mx0 - mn0 + 1e-5f) > 0.5f) ? 1.0f : 0.0f;
    mrow[(a0 + 1) * NA + c] = ((s1 - mn1) / (mx1 - mn1 + 1e-5f) > 0.5f) ? 1.0f : 0.0f;
}

// ---------------- launch ------------------------------------------------------
extern "C" void kernel_launch(void* const* d_in, const int* in_sizes, int n_in,
                              void* d_out, int out_size) {
    const float* X  = (const float*)d_in[0];
    const int*   ei = (const int*)d_in[1];
    const float* W  = (const float*)d_in[2];
    const float* bv = (const float*)d_in[3];
    float* out = (float*)d_out;

    float* Xo;
    float* mask;
    if (out_size >= XO_ELEMS + MASK_ELEMS) {
        Xo = out;
        mask = out + XO_ELEMS;
    } else if (out_size >= XO_ELEMS) {
        Xo = out;
        float* dummy; cudaGetSymbolAddress((void**)&dummy, g_mask_scratch);
        mask = dummy;
    } else {
        float* dummy; cudaGetSymbolAddress((void**)&dummy, g_Xo_scratch);
        Xo = dummy;
        mask = out;
    }

    // one-time host-side infra (no device allocation)
    static cudaStream_t s2 = nullptr;
    static cudaEvent_t evFork = nullptr, evJoin = nullptr;
    if (s2 == nullptr) {
        cudaStreamCreateWithFlags(&s2, cudaStreamNonBlocking);
        cudaEventCreateWithFlags(&evFork, cudaEventDisableTiming);
        cudaEventCreateWithFlags(&evJoin, cudaEventDisableTiming);
    }

    void* degp;
    cudaGetSymbolAddress(&degp, g_deg);

    // fork: GEMM on s2 runs concurrently with memset+scatter+dinv on default
    cudaEventRecord(evFork, 0);
    cudaStreamWaitEvent(s2, evFork, 0);
    dim3 gg(NN / 128, 256 / 128);       // (128, 2) = 256 CTAs, 2 CTAs/SM
    k_gemm<<<gg, 256, 0, s2>>>(X, W);
    cudaEventRecord(evJoin, s2);

    cudaMemsetAsync(degp, 0, NN * sizeof(int));
    k_scatter<<<NE / 256, 256>>>(ei);
    k_dinv<<<NN / 512, 512>>>();

    // join: aggregate needs both Y (s2) and slots/dinv (default)
    cudaStreamWaitEvent(0, evJoin, 0);
    k_aggregate<<<(NN * 32) / 256, 256>>>(bv, Xo);
    k_adj<<<NB, 512>>>(Xo, mask);
}